// round 1
// baseline (speedup 1.0000x reference)
#include <cuda_runtime.h>
#include <cuda_bf16.h>
#include <math.h>

// ---------------- problem constants ----------------
#define B_      64
#define EVI_    5
#define SEQS_   (B_ * EVI_)          // 320
#define L_      256
#define D_      768
#define WORDS_  32
#define TPW_    4
#define NN_     (SEQS_ * WORDS_)     // 10240 nodes
#define EE_     (NN_ * 16)           // 163840 edges
#define R_      4
#define DOUT_   768
#define LH_     1024
#define NC_     3

// ---------------- scratch (device globals; no allocs allowed) ----------------
__device__ float g_x   [(size_t)NN_ * D_];          // 30 MB : x0, then layer-2 accumulator / x2
__device__ float g_acc [(size_t)NN_ * D_];          // 30 MB : layer-1 accumulator / x1
__device__ float g_h   [(size_t)R_ * NN_ * D_];     // 120 MB: per-relation aggregation
__device__ int   g_cnt [NN_ * R_];
__device__ float g_inv [NN_ * R_];
__device__ float g_ev  [SEQS_ * 2 * DOUT_];         // (320,1536)
__device__ float g_attin[SEQS_ * (D_ + 2 * DOUT_)]; // (320,2304)
__device__ float g_hatt[SEQS_ * DOUT_];             // (320,768)
__device__ float g_p   [SEQS_];
__device__ float g_a   [SEQS_];
__device__ float g_rep [B_ * (2 * DOUT_ + D_)];     // (64,2304)
__device__ float g_hid [B_ * LH_];                  // (64,1024)

// ---------------- utility kernels ----------------
__global__ void zero4_kernel(float4* p, long long n4) {
    long long t = (long long)blockIdx.x * blockDim.x + threadIdx.x;
    if (t < n4) p[t] = make_float4(0.f, 0.f, 0.f, 0.f);
}

__global__ void relu_kernel(float* p, long long n) {
    long long t = (long long)blockIdx.x * blockDim.x + threadIdx.x;
    if (t < n) p[t] = fmaxf(p[t], 0.f);
}

__global__ void init_bias_kernel(float* C, const float* __restrict__ bias, long long M, int N) {
    long long t = (long long)blockIdx.x * blockDim.x + threadIdx.x;
    if (t < M * N) C[t] = bias[t % N];
}

// ---------------- graph prep ----------------
__global__ void count_kernel(const int* __restrict__ eidx, const int* __restrict__ etype) {
    int e = blockIdx.x * blockDim.x + threadIdx.x;
    if (e >= EE_) return;
    int dst = eidx[EE_ + e];
    int r   = etype[e];
    atomicAdd(&g_cnt[dst * R_ + r], 1);
}

__global__ void inv_kernel() {
    int i = blockIdx.x * blockDim.x + threadIdx.x;
    if (i >= NN_ * R_) return;
    g_inv[i] = 1.f / (float)max(g_cnt[i], 1);
}

// x[n] = mean over 4 gathered token rows
__global__ void gather_mean_kernel(const float* __restrict__ tok, const int* __restrict__ wti) {
    long long t = (long long)blockIdx.x * blockDim.x + threadIdx.x;
    if (t >= (long long)NN_ * D_) return;
    int n = (int)(t / D_);
    int d = (int)(t % D_);
    const int* w = wti + n * TPW_;
    float s = tok[(size_t)w[0] * D_ + d] + tok[(size_t)w[1] * D_ + d]
            + tok[(size_t)w[2] * D_ + d] + tok[(size_t)w[3] * D_ + d];
    g_x[t] = 0.25f * s;
}

// h[r][dst] += x[src] * inv(dst,r), vectorized red.v4
__global__ void aggregate_kernel(const float* __restrict__ x,
                                 const int* __restrict__ eidx,
                                 const int* __restrict__ etype) {
    const int CH = D_ / 4; // 192 float4 chunks per edge
    long long t = (long long)blockIdx.x * blockDim.x + threadIdx.x;
    if (t >= (long long)EE_ * CH) return;
    int e = (int)(t / CH);
    int c = (int)(t % CH) * 4;
    int src = eidx[e];
    int dst = eidx[EE_ + e];
    int r   = etype[e];
    float s = g_inv[dst * R_ + r];
    float4 v = *(const float4*)(x + (size_t)src * D_ + c);
    float* hp = g_h + ((size_t)r * NN_ + dst) * D_ + c;
    asm volatile("red.global.add.v4.f32 [%0], {%1,%2,%3,%4};"
                 :: "l"(hp), "f"(v.x * s), "f"(v.y * s), "f"(v.z * s), "f"(v.w * s)
                 : "memory");
}

// ---------------- SGEMM: C += A(MxK) @ B(KxN), row-major, N%128==0, K%8==0 ----------------
#define BM 128
#define BN 128
#define BK 8
#define TM 8
#define TN 8

__global__ __launch_bounds__(256)
void sgemm_acc(const float* __restrict__ A, const float* __restrict__ Bm,
               float* __restrict__ C, int M, int N, int K) {
    const int brow = blockIdx.y, bcol = blockIdx.x;
    const int tid = threadIdx.x;
    __shared__ float As[BK][BM];
    __shared__ float Bs[BK][BN];
    const int threadRow = tid / (BN / TN);
    const int threadCol = tid % (BN / TN);
    const int aRow = tid >> 1;
    const int aCol = (tid & 1) * 4;
    const int bRow = tid >> 5;
    const int bCol = (tid & 31) * 4;

    float acc[TM][TN] = {};
    float regM[TM], regN[TN];

    const int gARow = brow * BM + aRow;
    const bool aValid = (gARow < M);
    const float* Aptr = A + (size_t)gARow * K;
    const float* Bptr = Bm + bcol * BN;

    for (int k0 = 0; k0 < K; k0 += BK) {
        float4 av = aValid ? *(const float4*)(Aptr + k0 + aCol) : make_float4(0.f, 0.f, 0.f, 0.f);
        As[aCol + 0][aRow] = av.x;
        As[aCol + 1][aRow] = av.y;
        As[aCol + 2][aRow] = av.z;
        As[aCol + 3][aRow] = av.w;
        *(float4*)&Bs[bRow][bCol] = *(const float4*)(Bptr + (size_t)(k0 + bRow) * N + bCol);
        __syncthreads();
#pragma unroll
        for (int k = 0; k < BK; ++k) {
#pragma unroll
            for (int i = 0; i < TM; ++i) regM[i] = As[k][threadRow * TM + i];
#pragma unroll
            for (int j = 0; j < TN; ++j) regN[j] = Bs[k][threadCol * TN + j];
#pragma unroll
            for (int i = 0; i < TM; ++i)
#pragma unroll
                for (int j = 0; j < TN; ++j)
                    acc[i][j] += regM[i] * regN[j];
        }
        __syncthreads();
    }
#pragma unroll
    for (int i = 0; i < TM; ++i) {
        int r = brow * BM + threadRow * TM + i;
        if (r < M) {
            float* Cp = C + (size_t)r * N + bcol * BN + threadCol * TN;
#pragma unroll
            for (int j = 0; j < TN; j += 4) {
                float4 cv = *(float4*)(Cp + j);
                cv.x += acc[i][j + 0];
                cv.y += acc[i][j + 1];
                cv.z += acc[i][j + 2];
                cv.w += acc[i][j + 3];
                *(float4*)(Cp + j) = cv;
            }
        }
    }
}

// ---------------- head kernels ----------------
// ev = [mean over 32 words | max over 32 words] of x2 per sequence
__global__ void ev_pool_kernel() {
    int t = blockIdx.x * blockDim.x + threadIdx.x;
    if (t >= SEQS_ * DOUT_) return;
    int s = t / DOUT_, d = t % DOUT_;
    const float* base = g_x + (size_t)s * WORDS_ * DOUT_ + d;
    float sum = 0.f, mx = -1e30f;
#pragma unroll 8
    for (int w = 0; w < WORDS_; ++w) {
        float v = base[(size_t)w * DOUT_];
        sum += v;
        mx = fmaxf(mx, v);
    }
    g_ev[s * (2 * DOUT_) + d]         = sum * (1.f / WORDS_);
    g_ev[s * (2 * DOUT_) + DOUT_ + d] = mx;
}

__global__ void build_attin_kernel(const float* __restrict__ tok, const int* __restrict__ csi) {
    int t = blockIdx.x * blockDim.x + threadIdx.x;
    const int W = D_ + 2 * DOUT_; // 2304
    if (t >= SEQS_ * W) return;
    int s = t / W, c = t % W;
    if (c < D_) {
        int seq = csi[s / EVI_];
        g_attin[t] = tok[(size_t)seq * L_ * D_ + c]; // token 0 of claim sequence
    } else {
        g_attin[t] = g_ev[s * (2 * DOUT_) + (c - D_)];
    }
}

__global__ void dotp_kernel(const float* __restrict__ att_w1) {
    int s = blockIdx.x;
    int tid = threadIdx.x; // 256
    float acc = 0.f;
    for (int k = tid; k < DOUT_; k += 256)
        acc += g_hatt[(size_t)s * DOUT_ + k] * att_w1[k];
#pragma unroll
    for (int o = 16; o; o >>= 1) acc += __shfl_down_sync(0xffffffffu, acc, o);
    __shared__ float sw[8];
    if ((tid & 31) == 0) sw[tid >> 5] = acc;
    __syncthreads();
    if (tid == 0) {
        float r = 0.f;
#pragma unroll
        for (int w = 0; w < 8; ++w) r += sw[w];
        g_p[s] = r;
    }
}

// softmax over EVI per batch -> g_a ; sigmoid(p) -> out[192 + i]
__global__ void softmax_att_kernel(float* __restrict__ out) {
    int b = blockIdx.x;
    if (threadIdx.x != 0) return;
    float pv[EVI_];
    float m = -1e30f;
#pragma unroll
    for (int e = 0; e < EVI_; ++e) { pv[e] = g_p[b * EVI_ + e]; m = fmaxf(m, pv[e]); }
    float s = 0.f;
#pragma unroll
    for (int e = 0; e < EVI_; ++e) { pv[e] = expf(pv[e] - m); s += pv[e]; }
    float is = 1.f / s;
#pragma unroll
    for (int e = 0; e < EVI_; ++e) {
        g_a[b * EVI_ + e] = pv[e] * is;
        float p = g_p[b * EVI_ + e];
        out[B_ * NC_ + b * EVI_ + e] = 1.f / (1.f + expf(-p));
    }
}

__global__ void graph_rep_kernel(const float* __restrict__ concat_cls) {
    int t = blockIdx.x * blockDim.x + threadIdx.x;
    const int W = 2 * DOUT_ + D_; // 2304
    if (t >= B_ * W) return;
    int b = t / W, c = t % W;
    if (c < 2 * DOUT_) {
        float acc = 0.f;
#pragma unroll
        for (int e = 0; e < EVI_; ++e)
            acc += g_a[b * EVI_ + e] * g_ev[(size_t)(b * EVI_ + e) * (2 * DOUT_) + c];
        g_rep[t] = acc;
    } else {
        g_rep[t] = concat_cls[b * D_ + (c - 2 * DOUT_)];
    }
}

__global__ void final_kernel(const float* __restrict__ lin2_w,
                             const float* __restrict__ lin2_b,
                             float* __restrict__ out) {
    int b = blockIdx.x;
    int tid = threadIdx.x; // 128
    float a0 = 0.f, a1 = 0.f, a2 = 0.f;
    for (int k = tid; k < LH_; k += 128) {
        float h = g_hid[(size_t)b * LH_ + k];
        a0 += h * lin2_w[k * NC_ + 0];
        a1 += h * lin2_w[k * NC_ + 1];
        a2 += h * lin2_w[k * NC_ + 2];
    }
#pragma unroll
    for (int o = 16; o; o >>= 1) {
        a0 += __shfl_down_sync(0xffffffffu, a0, o);
        a1 += __shfl_down_sync(0xffffffffu, a1, o);
        a2 += __shfl_down_sync(0xffffffffu, a2, o);
    }
    __shared__ float s0[4], s1[4], s2[4];
    if ((tid & 31) == 0) { int w = tid >> 5; s0[w] = a0; s1[w] = a1; s2[w] = a2; }
    __syncthreads();
    if (tid == 0) {
        float l0 = s0[0] + s0[1] + s0[2] + s0[3] + lin2_b[0];
        float l1 = s1[0] + s1[1] + s1[2] + s1[3] + lin2_b[1];
        float l2 = s2[0] + s2[1] + s2[2] + s2[3] + lin2_b[2];
        float m = fmaxf(l0, fmaxf(l1, l2));
        float lse = logf(expf(l0 - m) + expf(l1 - m) + expf(l2 - m)) + m;
        out[b * NC_ + 0] = l0 - m - lse + m; // = l0 - (m + lse_shifted)
        out[b * NC_ + 0] = l0 - (m + lse - m); // keep simple below
        out[b * NC_ + 0] = l0 - lse;
        out[b * NC_ + 1] = l1 - lse;
        out[b * NC_ + 2] = l2 - lse;
    }
}

// ---------------- launch ----------------
static inline dim3 gemm_grid(int M, int N) {
    return dim3((N + BN - 1) / BN, (M + BM - 1) / BM);
}

extern "C" void kernel_launch(void* const* d_in, const int* in_sizes, int n_in,
                              void* d_out, int out_size) {
    const float* token_feats = (const float*)d_in[0];
    const float* concat_cls  = (const float*)d_in[1];
    const float* W_rel1      = (const float*)d_in[2];
    const float* W_root1     = (const float*)d_in[3];
    const float* b1          = (const float*)d_in[4];
    const float* W_rel2      = (const float*)d_in[5];
    const float* W_root2     = (const float*)d_in[6];
    const float* b2          = (const float*)d_in[7];
    const float* att_w0      = (const float*)d_in[8];
    const float* att_w1      = (const float*)d_in[9];
    const float* lin1_w      = (const float*)d_in[10];
    const float* lin1_b      = (const float*)d_in[11];
    const float* lin2_w      = (const float*)d_in[12];
    const float* lin2_b      = (const float*)d_in[13];
    const int*   wti         = (const int*)d_in[14];
    const int*   eidx        = (const int*)d_in[15];
    const int*   etype       = (const int*)d_in[16];
    const int*   csi         = (const int*)d_in[17];
    float* out = (float*)d_out;

    float *p_x, *p_acc, *p_h, *p_cnt, *p_ev, *p_attin, *p_hatt, *p_rep, *p_hid;
    cudaGetSymbolAddress((void**)&p_x,     g_x);
    cudaGetSymbolAddress((void**)&p_acc,   g_acc);
    cudaGetSymbolAddress((void**)&p_h,     g_h);
    cudaGetSymbolAddress((void**)&p_cnt,   g_cnt);
    cudaGetSymbolAddress((void**)&p_ev,    g_ev);
    cudaGetSymbolAddress((void**)&p_attin, g_attin);
    cudaGetSymbolAddress((void**)&p_hatt,  g_hatt);
    cudaGetSymbolAddress((void**)&p_rep,   g_rep);
    cudaGetSymbolAddress((void**)&p_hid,   g_hid);

    const int T = 256;
    const long long ND  = (long long)NN_ * D_;             // 7.86M
    const long long HSZ = (long long)R_ * NN_ * D_;         // 31.46M
    const long long AGG = (long long)EE_ * (D_ / 4);        // 31.46M threads

    // --- graph prep (cnt/inv identical for both layers) ---
    zero4_kernel<<<(NN_ * R_ / 4 + T - 1) / T, T>>>((float4*)p_cnt, NN_ * R_ / 4);
    count_kernel<<<(EE_ + T - 1) / T, T>>>(eidx, etype);
    inv_kernel<<<(NN_ * R_ + T - 1) / T, T>>>();

    // --- x0 = gathered word means ---
    gather_mean_kernel<<<(unsigned)((ND + T - 1) / T), T>>>(token_feats, wti);

    // --- layer 1 ---
    zero4_kernel<<<(unsigned)((HSZ / 4 + T - 1) / T), T>>>((float4*)p_h, HSZ / 4);
    aggregate_kernel<<<(unsigned)((AGG + T - 1) / T), T>>>(p_x, eidx, etype);
    init_bias_kernel<<<(unsigned)((ND + T - 1) / T), T>>>(p_acc, b1, NN_, D_);
    for (int r = 0; r < R_; ++r)
        sgemm_acc<<<gemm_grid(NN_, D_), 256>>>(p_h + (size_t)r * NN_ * D_,
                                               W_rel1 + (size_t)r * D_ * D_,
                                               p_acc, NN_, D_, D_);
    sgemm_acc<<<gemm_grid(NN_, D_), 256>>>(p_x, W_root1, p_acc, NN_, D_, D_);
    relu_kernel<<<(unsigned)((ND + T - 1) / T), T>>>(p_acc, ND);

    // --- layer 2 (accumulate into g_x, x0 no longer needed) ---
    zero4_kernel<<<(unsigned)((HSZ / 4 + T - 1) / T), T>>>((float4*)p_h, HSZ / 4);
    aggregate_kernel<<<(unsigned)((AGG + T - 1) / T), T>>>(p_acc, eidx, etype);
    init_bias_kernel<<<(unsigned)((ND + T - 1) / T), T>>>(p_x, b2, NN_, DOUT_);
    for (int r = 0; r < R_; ++r)
        sgemm_acc<<<gemm_grid(NN_, DOUT_), 256>>>(p_h + (size_t)r * NN_ * D_,
                                                  W_rel2 + (size_t)r * D_ * DOUT_,
                                                  p_x, NN_, DOUT_, D_);
    sgemm_acc<<<gemm_grid(NN_, DOUT_), 256>>>(p_acc, W_root2, p_x, NN_, DOUT_, D_);
    relu_kernel<<<(unsigned)((ND + T - 1) / T), T>>>(p_x, ND);

    // --- evidence pooling + attention ---
    ev_pool_kernel<<<(SEQS_ * DOUT_ + T - 1) / T, T>>>();
    build_attin_kernel<<<(SEQS_ * (D_ + 2 * DOUT_) + T - 1) / T, T>>>(token_feats, csi);
    zero4_kernel<<<(SEQS_ * DOUT_ / 4 + T - 1) / T, T>>>((float4*)p_hatt, SEQS_ * DOUT_ / 4);
    sgemm_acc<<<gemm_grid(SEQS_, DOUT_), 256>>>(p_attin, att_w0, p_hatt,
                                                SEQS_, DOUT_, D_ + 2 * DOUT_);
    relu_kernel<<<(SEQS_ * DOUT_ + T - 1) / T, T>>>(p_hatt, (long long)SEQS_ * DOUT_);
    dotp_kernel<<<SEQS_, 256>>>(att_w1);
    softmax_att_kernel<<<B_, 32>>>(out);

    // --- graph readout + classifier ---
    graph_rep_kernel<<<(B_ * (2 * DOUT_ + D_) + T - 1) / T, T>>>(concat_cls);
    init_bias_kernel<<<(B_ * LH_ + T - 1) / T, T>>>(p_hid, lin1_b, B_, LH_);
    sgemm_acc<<<gemm_grid(B_, LH_), 256>>>(p_rep, lin1_w, p_hid, B_, LH_, 2 * DOUT_ + D_);
    relu_kernel<<<(B_ * LH_ + T - 1) / T, T>>>(p_hid, (long long)B_ * LH_);
    final_kernel<<<B_, 128>>>(lin2_w, lin2_b, out);
}

// round 3
// speedup vs baseline: 1.8449x; 1.8449x over previous
#include <cuda_runtime.h>
#include <cuda_bf16.h>
#include <math.h>
#include <stdint.h>

// ---------------- problem constants ----------------
#define B_      64
#define EVI_    5
#define SEQS_   (B_ * EVI_)          // 320
#define L_      256
#define D_      768
#define WORDS_  32
#define TPW_    4
#define NN_     (SEQS_ * WORDS_)     // 10240 nodes
#define EE_     (NN_ * 16)           // 163840 edges
#define R_      4
#define DOUT_   768
#define LH_     1024
#define NC_     3
#define KTOT_   (5 * D_)             // 3840 fused K

// ---------------- scratch (device globals; no allocs allowed) ----------------
__device__ float g_x   [(size_t)NN_ * D_];          // x0 / x2
__device__ float g_acc [(size_t)NN_ * D_];          // x1
__device__ float g_h   [(size_t)R_ * NN_ * D_];     // per-relation aggregation
__device__ int   g_cnt [NN_ * R_];
__device__ float g_inv [NN_ * R_];
__device__ float g_ev  [SEQS_ * 2 * DOUT_];
__device__ float g_attin[SEQS_ * (D_ + 2 * DOUT_)];
__device__ float g_hatt[SEQS_ * DOUT_];
__device__ float g_p   [SEQS_];
__device__ float g_a   [SEQS_];
__device__ float g_rep [B_ * (2 * DOUT_ + D_)];
__device__ float g_hid [B_ * LH_];

// ---------------- utility kernels ----------------
__global__ void zero4_kernel(float4* p, long long n4) {
    long long t = (long long)blockIdx.x * blockDim.x + threadIdx.x;
    if (t < n4) p[t] = make_float4(0.f, 0.f, 0.f, 0.f);
}
__global__ void relu_kernel(float* p, long long n) {
    long long t = (long long)blockIdx.x * blockDim.x + threadIdx.x;
    if (t < n) p[t] = fmaxf(p[t], 0.f);
}
__global__ void init_bias_kernel(float* C, const float* __restrict__ bias, long long M, int N) {
    long long t = (long long)blockIdx.x * blockDim.x + threadIdx.x;
    if (t < M * N) C[t] = bias[t % N];
}

// ---------------- graph prep ----------------
__global__ void count_kernel(const int* __restrict__ eidx, const int* __restrict__ etype) {
    int e = blockIdx.x * blockDim.x + threadIdx.x;
    if (e >= EE_) return;
    atomicAdd(&g_cnt[eidx[EE_ + e] * R_ + etype[e]], 1);
}
__global__ void inv_kernel() {
    int i = blockIdx.x * blockDim.x + threadIdx.x;
    if (i >= NN_ * R_) return;
    g_inv[i] = 1.f / (float)max(g_cnt[i], 1);
}
__global__ void gather_mean_kernel(const float* __restrict__ tok, const int* __restrict__ wti) {
    long long t = (long long)blockIdx.x * blockDim.x + threadIdx.x;
    if (t >= (long long)NN_ * D_) return;
    int n = (int)(t / D_);
    int d = (int)(t % D_);
    const int* w = wti + n * TPW_;
    float s = tok[(size_t)w[0] * D_ + d] + tok[(size_t)w[1] * D_ + d]
            + tok[(size_t)w[2] * D_ + d] + tok[(size_t)w[3] * D_ + d];
    g_x[t] = 0.25f * s;
}
__global__ void aggregate_kernel(const float* __restrict__ x,
                                 const int* __restrict__ eidx,
                                 const int* __restrict__ etype) {
    const int CH = D_ / 4;
    long long t = (long long)blockIdx.x * blockDim.x + threadIdx.x;
    if (t >= (long long)EE_ * CH) return;
    int e = (int)(t / CH);
    int c = (int)(t % CH) * 4;
    int src = eidx[e];
    int dst = eidx[EE_ + e];
    int r   = etype[e];
    float s = g_inv[dst * R_ + r];
    float4 v = *(const float4*)(x + (size_t)src * D_ + c);
    float* hp = g_h + ((size_t)r * NN_ + dst) * D_ + c;
    asm volatile("red.global.add.v4.f32 [%0], {%1,%2,%3,%4};"
                 :: "l"(hp), "f"(v.x * s), "f"(v.y * s), "f"(v.z * s), "f"(v.w * s)
                 : "memory");
}

// ---------------- split-bf16 tensor-core GEMM via mma.sync (sm_80+ path) ----------------
// C(NN_ x 768) = relu( A_cat(NN_ x 3840) @ Wcat(3840 x 768) + bias )
// A_cat[n][k] = (k<3072) ? g_h[k/768][n][k%768] : xroot[n][k%768]
// Wcat[k][e]  = (k<3072) ? W_rel[k/768][k%768][e] : W_root[k%768][e]
// fp32 -> (hi,lo) bf16 split in registers during smem staging; 3 mma passes.

#define GBM 128
#define GBN 256
#define GBK 32
#define NSTG (KTOT_ / GBK)   // 120
#define AP_  20              // A smem pitch in u32 (16 + 4 pad) -> conflict-free frags
#define BP_  264             // B smem pitch in u32 (256 + 8 pad)
#define ASZ_ (GBM * AP_)     // 2560 u32
#define BSZ_ (16 * BP_)      // 4224 u32
#define GSMEM ((2 * ASZ_ + 2 * BSZ_) * 4)   // 54272 bytes

__device__ __forceinline__ uint32_t pack2(float lo, float hi) {
    // result = {lo in low 16, hi in high 16}; first asm source -> high half
    uint32_t r;
    asm("cvt.rn.bf16x2.f32 %0, %1, %2;" : "=r"(r) : "f"(hi), "f"(lo));
    return r;
}
__device__ __forceinline__ void mma16816(float* c, const uint32_t* a, const uint32_t* b) {
    asm volatile("mma.sync.aligned.m16n8k16.row.col.f32.bf16.bf16.f32 "
                 "{%0,%1,%2,%3}, {%4,%5,%6,%7}, {%8,%9}, {%0,%1,%2,%3};"
                 : "+f"(c[0]), "+f"(c[1]), "+f"(c[2]), "+f"(c[3])
                 : "r"(a[0]), "r"(a[1]), "r"(a[2]), "r"(a[3]), "r"(b[0]), "r"(b[1]));
}

__global__ void __launch_bounds__(256, 1)
gemm_rgcn(const float* __restrict__ gh, const float* __restrict__ xroot,
          const float* __restrict__ Wrel, const float* __restrict__ Wroot,
          const float* __restrict__ bias, float* __restrict__ C) {
    extern __shared__ uint32_t sm[];
    uint32_t* AsH = sm;
    uint32_t* AsL = AsH + ASZ_;
    uint32_t* BsH = AsL + ASZ_;
    uint32_t* BsL = BsH + BSZ_;

    const int tid  = threadIdx.x;
    const int wid  = tid >> 5;
    const int lane = tid & 31;
    const int g    = lane >> 2;      // group row
    const int tc   = lane & 3;       // thread col
    const int wm   = wid & 1;        // warp m (0..1) -> 64 rows
    const int wn   = wid >> 1;       // warp n (0..3) -> 64 cols
    const int m0   = blockIdx.y * GBM;
    const int n0   = blockIdx.x * GBN;

    float acc[4][8][4];
#pragma unroll
    for (int i = 0; i < 4; ++i)
#pragma unroll
        for (int j = 0; j < 8; ++j)
#pragma unroll
            for (int q = 0; q < 4; ++q) acc[i][j][q] = 0.f;

    for (int kc = 0; kc < NSTG; ++kc) {
        const int k0 = kc * GBK;
        const int r  = k0 / D_;
        const int d0 = k0 - r * D_;

        __syncthreads();
        // ---- stage A tile: 128 x 32 fp32 -> split bf16, pack along k ----
        {
            const float* Ab = (r < 4) ? (gh + ((size_t)r * NN_ + m0) * D_ + d0)
                                      : (xroot + (size_t)m0 * D_ + d0);
#pragma unroll
            for (int c = tid; c < 1024; c += 256) {
                int m  = c >> 3;
                int kq = c & 7;
                float4 v = *(const float4*)(Ab + (size_t)m * D_ + kq * 4);
                uint32_t h0 = pack2(v.x, v.y);
                uint32_t h1 = pack2(v.z, v.w);
                float rx = v.x - __uint_as_float(h0 << 16);
                float ry = v.y - __uint_as_float(h0 & 0xFFFF0000u);
                float rz = v.z - __uint_as_float(h1 << 16);
                float rw = v.w - __uint_as_float(h1 & 0xFFFF0000u);
                uint32_t l0 = pack2(rx, ry);
                uint32_t l1 = pack2(rz, rw);
                int off = m * AP_ + kq * 2;
                *(uint2*)&AsH[off] = make_uint2(h0, h1);
                *(uint2*)&AsL[off] = make_uint2(l0, l1);
            }
        }
        // ---- stage B tile: 32 x 256 fp32 (k-major rows) -> pack pairs of k ----
        {
            const float* Wb = (r < 4) ? (Wrel + ((size_t)r * D_ + d0) * D_ + n0)
                                      : (Wroot + (size_t)d0 * D_ + n0);
#pragma unroll
            for (int c = tid; c < 1024; c += 256) {
                int k2 = c >> 6;
                int nq = (c & 63) * 4;
                const float* w0 = Wb + (size_t)(2 * k2) * D_ + nq;
                float4 va = *(const float4*)w0;
                float4 vb = *(const float4*)(w0 + D_);
                uint32_t h0 = pack2(va.x, vb.x);
                uint32_t h1 = pack2(va.y, vb.y);
                uint32_t h2 = pack2(va.z, vb.z);
                uint32_t h3 = pack2(va.w, vb.w);
                uint32_t l0 = pack2(va.x - __uint_as_float(h0 << 16), vb.x - __uint_as_float(h0 & 0xFFFF0000u));
                uint32_t l1 = pack2(va.y - __uint_as_float(h1 << 16), vb.y - __uint_as_float(h1 & 0xFFFF0000u));
                uint32_t l2 = pack2(va.z - __uint_as_float(h2 << 16), vb.z - __uint_as_float(h2 & 0xFFFF0000u));
                uint32_t l3 = pack2(va.w - __uint_as_float(h3 << 16), vb.w - __uint_as_float(h3 & 0xFFFF0000u));
                int off = k2 * BP_ + nq;
                *(uint4*)&BsH[off] = make_uint4(h0, h1, h2, h3);
                *(uint4*)&BsL[off] = make_uint4(l0, l1, l2, l3);
            }
        }
        __syncthreads();

        // ---- compute: 2 k-steps of 16, 3 passes each ----
#pragma unroll
        for (int ks = 0; ks < 2; ++ks) {
            const int kb = ks * 8;
            uint32_t aH[4][4], aL[4][4], bH[8][2], bL[8][2];
#pragma unroll
            for (int mt = 0; mt < 4; ++mt) {
                int rb = wm * 64 + mt * 16;
                int i0 = (rb + g) * AP_ + kb + tc;
                int i1 = (rb + 8 + g) * AP_ + kb + tc;
                aH[mt][0] = AsH[i0]; aH[mt][1] = AsH[i1];
                aH[mt][2] = AsH[i0 + 4]; aH[mt][3] = AsH[i1 + 4];
                aL[mt][0] = AsL[i0]; aL[mt][1] = AsL[i1];
                aL[mt][2] = AsL[i0 + 4]; aL[mt][3] = AsL[i1 + 4];
            }
#pragma unroll
            for (int nt = 0; nt < 8; ++nt) {
                int cb = wn * 64 + nt * 8;
                int j0 = (kb + tc) * BP_ + cb + g;
                int j1 = (kb + 4 + tc) * BP_ + cb + g;
                bH[nt][0] = BsH[j0]; bH[nt][1] = BsH[j1];
                bL[nt][0] = BsL[j0]; bL[nt][1] = BsL[j1];
            }
#pragma unroll
            for (int mt = 0; mt < 4; ++mt)
#pragma unroll
                for (int nt = 0; nt < 8; ++nt) {
                    mma16816(acc[mt][nt], aH[mt], bH[nt]);
                    mma16816(acc[mt][nt], aH[mt], bL[nt]);
                    mma16816(acc[mt][nt], aL[mt], bH[nt]);
                }
        }
    }

    // ---- epilogue: bias + relu, fp32 out ----
#pragma unroll
    for (int mt = 0; mt < 4; ++mt) {
        int row = m0 + wm * 64 + mt * 16 + g;
#pragma unroll
        for (int nt = 0; nt < 8; ++nt) {
            int col = n0 + wn * 64 + nt * 8 + tc * 2;
            float b0 = __ldg(bias + col);
            float b1 = __ldg(bias + col + 1);
            float2 v0 = make_float2(fmaxf(acc[mt][nt][0] + b0, 0.f),
                                    fmaxf(acc[mt][nt][1] + b1, 0.f));
            float2 v1 = make_float2(fmaxf(acc[mt][nt][2] + b0, 0.f),
                                    fmaxf(acc[mt][nt][3] + b1, 0.f));
            *(float2*)(C + (size_t)row * D_ + col)       = v0;
            *(float2*)(C + (size_t)(row + 8) * D_ + col) = v1;
        }
    }
}

// ---------------- fp32 SGEMM for small head GEMMs ----------------
#define BM 128
#define BN 128
#define BK 8
#define TM 8
#define TN 8
__global__ __launch_bounds__(256)
void sgemm_acc(const float* __restrict__ A, const float* __restrict__ Bm,
               float* __restrict__ C, int M, int N, int K) {
    const int brow = blockIdx.y, bcol = blockIdx.x;
    const int tid = threadIdx.x;
    __shared__ float As[BK][BM];
    __shared__ float Bs[BK][BN];
    const int threadRow = tid / (BN / TN);
    const int threadCol = tid % (BN / TN);
    const int aRow = tid >> 1;
    const int aCol = (tid & 1) * 4;
    const int bRow = tid >> 5;
    const int bCol = (tid & 31) * 4;
    float acc[TM][TN] = {};
    float regM[TM], regN[TN];
    const int gARow = brow * BM + aRow;
    const bool aValid = (gARow < M);
    const float* Aptr = A + (size_t)gARow * K;
    const float* Bptr = Bm + bcol * BN;
    for (int k0 = 0; k0 < K; k0 += BK) {
        float4 av = aValid ? *(const float4*)(Aptr + k0 + aCol) : make_float4(0.f, 0.f, 0.f, 0.f);
        As[aCol + 0][aRow] = av.x;
        As[aCol + 1][aRow] = av.y;
        As[aCol + 2][aRow] = av.z;
        As[aCol + 3][aRow] = av.w;
        *(float4*)&Bs[bRow][bCol] = *(const float4*)(Bptr + (size_t)(k0 + bRow) * N + bCol);
        __syncthreads();
#pragma unroll
        for (int k = 0; k < BK; ++k) {
#pragma unroll
            for (int i = 0; i < TM; ++i) regM[i] = As[k][threadRow * TM + i];
#pragma unroll
            for (int j = 0; j < TN; ++j) regN[j] = Bs[k][threadCol * TN + j];
#pragma unroll
            for (int i = 0; i < TM; ++i)
#pragma unroll
                for (int j = 0; j < TN; ++j)
                    acc[i][j] += regM[i] * regN[j];
        }
        __syncthreads();
    }
#pragma unroll
    for (int i = 0; i < TM; ++i) {
        int r = brow * BM + threadRow * TM + i;
        if (r < M) {
            float* Cp = C + (size_t)r * N + bcol * BN + threadCol * TN;
#pragma unroll
            for (int j = 0; j < TN; j += 4) {
                float4 cv = *(float4*)(Cp + j);
                cv.x += acc[i][j + 0];
                cv.y += acc[i][j + 1];
                cv.z += acc[i][j + 2];
                cv.w += acc[i][j + 3];
                *(float4*)(Cp + j) = cv;
            }
        }
    }
}

// ---------------- head kernels ----------------
__global__ void ev_pool_kernel() {
    int t = blockIdx.x * blockDim.x + threadIdx.x;
    if (t >= SEQS_ * DOUT_) return;
    int s = t / DOUT_, d = t % DOUT_;
    const float* base = g_x + (size_t)s * WORDS_ * DOUT_ + d;
    float sum = 0.f, mx = -1e30f;
#pragma unroll 8
    for (int w = 0; w < WORDS_; ++w) {
        float v = base[(size_t)w * DOUT_];
        sum += v;
        mx = fmaxf(mx, v);
    }
    g_ev[s * (2 * DOUT_) + d]         = sum * (1.f / WORDS_);
    g_ev[s * (2 * DOUT_) + DOUT_ + d] = mx;
}
__global__ void build_attin_kernel(const float* __restrict__ tok, const int* __restrict__ csi) {
    int t = blockIdx.x * blockDim.x + threadIdx.x;
    const int W = D_ + 2 * DOUT_;
    if (t >= SEQS_ * W) return;
    int s = t / W, c = t % W;
    if (c < D_) {
        int seq = csi[s / EVI_];
        g_attin[t] = tok[(size_t)seq * L_ * D_ + c];
    } else {
        g_attin[t] = g_ev[s * (2 * DOUT_) + (c - D_)];
    }
}
__global__ void dotp_kernel(const float* __restrict__ att_w1) {
    int s = blockIdx.x;
    int tid = threadIdx.x;
    float acc = 0.f;
    for (int k = tid; k < DOUT_; k += 256)
        acc += g_hatt[(size_t)s * DOUT_ + k] * att_w1[k];
#pragma unroll
    for (int o = 16; o; o >>= 1) acc += __shfl_down_sync(0xffffffffu, acc, o);
    __shared__ float sw[8];
    if ((tid & 31) == 0) sw[tid >> 5] = acc;
    __syncthreads();
    if (tid == 0) {
        float r = 0.f;
#pragma unroll
        for (int w = 0; w < 8; ++w) r += sw[w];
        g_p[s] = r;
    }
}
__global__ void softmax_att_kernel(float* __restrict__ out) {
    int b = blockIdx.x;
    if (threadIdx.x != 0) return;
    float pv[EVI_];
    float m = -1e30f;
#pragma unroll
    for (int e = 0; e < EVI_; ++e) { pv[e] = g_p[b * EVI_ + e]; m = fmaxf(m, pv[e]); }
    float s = 0.f;
#pragma unroll
    for (int e = 0; e < EVI_; ++e) { pv[e] = expf(pv[e] - m); s += pv[e]; }
    float is = 1.f / s;
#pragma unroll
    for (int e = 0; e < EVI_; ++e) {
        g_a[b * EVI_ + e] = pv[e] * is;
        float p = g_p[b * EVI_ + e];
        out[B_ * NC_ + b * EVI_ + e] = 1.f / (1.f + expf(-p));
    }
}
__global__ void graph_rep_kernel(const float* __restrict__ concat_cls) {
    int t = blockIdx.x * blockDim.x + threadIdx.x;
    const int W = 2 * DOUT_ + D_;
    if (t >= B_ * W) return;
    int b = t / W, c = t % W;
    if (c < 2 * DOUT_) {
        float acc = 0.f;
#pragma unroll
        for (int e = 0; e < EVI_; ++e)
            acc += g_a[b * EVI_ + e] * g_ev[(size_t)(b * EVI_ + e) * (2 * DOUT_) + c];
        g_rep[t] = acc;
    } else {
        g_rep[t] = concat_cls[b * D_ + (c - 2 * DOUT_)];
    }
}
__global__ void final_kernel(const float* __restrict__ lin2_w,
                             const float* __restrict__ lin2_b,
                             float* __restrict__ out) {
    int b = blockIdx.x;
    int tid = threadIdx.x;
    float a0 = 0.f, a1 = 0.f, a2 = 0.f;
    for (int k = tid; k < LH_; k += 128) {
        float h = g_hid[(size_t)b * LH_ + k];
        a0 += h * lin2_w[k * NC_ + 0];
        a1 += h * lin2_w[k * NC_ + 1];
        a2 += h * lin2_w[k * NC_ + 2];
    }
#pragma unroll
    for (int o = 16; o; o >>= 1) {
        a0 += __shfl_down_sync(0xffffffffu, a0, o);
        a1 += __shfl_down_sync(0xffffffffu, a1, o);
        a2 += __shfl_down_sync(0xffffffffu, a2, o);
    }
    __shared__ float s0[4], s1[4], s2[4];
    if ((tid & 31) == 0) { int w = tid >> 5; s0[w] = a0; s1[w] = a1; s2[w] = a2; }
    __syncthreads();
    if (tid == 0) {
        float l0 = s0[0] + s0[1] + s0[2] + s0[3] + lin2_b[0];
        float l1 = s1[0] + s1[1] + s1[2] + s1[3] + lin2_b[1];
        float l2 = s2[0] + s2[1] + s2[2] + s2[3] + lin2_b[2];
        float m = fmaxf(l0, fmaxf(l1, l2));
        float lse = logf(expf(l0 - m) + expf(l1 - m) + expf(l2 - m)) + m;
        out[b * NC_ + 0] = l0 - lse;
        out[b * NC_ + 1] = l1 - lse;
        out[b * NC_ + 2] = l2 - lse;
    }
}

// ---------------- launch ----------------
static inline dim3 gemm_grid_f32(int M, int N) {
    return dim3((N + BN - 1) / BN, (M + BM - 1) / BM);
}

extern "C" void kernel_launch(void* const* d_in, const int* in_sizes, int n_in,
                              void* d_out, int out_size) {
    const float* token_feats = (const float*)d_in[0];
    const float* concat_cls  = (const float*)d_in[1];
    const float* W_rel1      = (const float*)d_in[2];
    const float* W_root1     = (const float*)d_in[3];
    const float* b1          = (const float*)d_in[4];
    const float* W_rel2      = (const float*)d_in[5];
    const float* W_root2     = (const float*)d_in[6];
    const float* b2          = (const float*)d_in[7];
    const float* att_w0      = (const float*)d_in[8];
    const float* att_w1      = (const float*)d_in[9];
    const float* lin1_w      = (const float*)d_in[10];
    const float* lin1_b      = (const float*)d_in[11];
    const float* lin2_w      = (const float*)d_in[12];
    const float* lin2_b      = (const float*)d_in[13];
    const int*   wti         = (const int*)d_in[14];
    const int*   eidx        = (const int*)d_in[15];
    const int*   etype       = (const int*)d_in[16];
    const int*   csi         = (const int*)d_in[17];
    float* out = (float*)d_out;

    float *p_x, *p_acc, *p_h, *p_attin, *p_hatt, *p_rep, *p_hid;
    int* p_cnt;
    cudaGetSymbolAddress((void**)&p_x,     g_x);
    cudaGetSymbolAddress((void**)&p_acc,   g_acc);
    cudaGetSymbolAddress((void**)&p_h,     g_h);
    cudaGetSymbolAddress((void**)&p_cnt,   g_cnt);
    cudaGetSymbolAddress((void**)&p_attin, g_attin);
    cudaGetSymbolAddress((void**)&p_hatt,  g_hatt);
    cudaGetSymbolAddress((void**)&p_rep,   g_rep);
    cudaGetSymbolAddress((void**)&p_hid,   g_hid);

    cudaFuncSetAttribute(gemm_rgcn, cudaFuncAttributeMaxDynamicSharedMemorySize, GSMEM);

    const int T = 256;
    const long long ND   = (long long)NN_ * D_;
    const long long HSZ  = (long long)R_ * NN_ * D_;
    const long long AGG  = (long long)EE_ * (D_ / 4);
    const dim3 ggrid(D_ / GBN, NN_ / GBM);   // (3, 80)

    // --- graph prep ---
    zero4_kernel<<<(NN_ * R_ / 4 + T - 1) / T, T>>>((float4*)p_cnt, NN_ * R_ / 4);
    count_kernel<<<(EE_ + T - 1) / T, T>>>(eidx, etype);
    inv_kernel<<<(NN_ * R_ + T - 1) / T, T>>>();

    // --- x0 ---
    gather_mean_kernel<<<(unsigned)((ND + T - 1) / T), T>>>(token_feats, wti);

    // --- layer 1 ---
    zero4_kernel<<<(unsigned)((HSZ / 4 + T - 1) / T), T>>>((float4*)p_h, HSZ / 4);
    aggregate_kernel<<<(unsigned)((AGG + T - 1) / T), T>>>(p_x, eidx, etype);
    gemm_rgcn<<<ggrid, 256, GSMEM>>>(p_h, p_x, W_rel1, W_root1, b1, p_acc);

    // --- layer 2 ---
    zero4_kernel<<<(unsigned)((HSZ / 4 + T - 1) / T), T>>>((float4*)p_h, HSZ / 4);
    aggregate_kernel<<<(unsigned)((AGG + T - 1) / T), T>>>(p_acc, eidx, etype);
    gemm_rgcn<<<ggrid, 256, GSMEM>>>(p_h, p_acc, W_rel2, W_root2, b2, p_x);

    // --- evidence pooling + attention (fp32, small) ---
    ev_pool_kernel<<<(SEQS_ * DOUT_ + T - 1) / T, T>>>();
    build_attin_kernel<<<(SEQS_ * (D_ + 2 * DOUT_) + T - 1) / T, T>>>(token_feats, csi);
    zero4_kernel<<<(SEQS_ * DOUT_ / 4 + T - 1) / T, T>>>((float4*)p_hatt, SEQS_ * DOUT_ / 4);
    sgemm_acc<<<gemm_grid_f32(SEQS_, DOUT_), 256>>>(p_attin, att_w0, p_hatt,
                                                    SEQS_, DOUT_, D_ + 2 * DOUT_);
    relu_kernel<<<(SEQS_ * DOUT_ + T - 1) / T, T>>>(p_hatt, (long long)SEQS_ * DOUT_);
    dotp_kernel<<<SEQS_, 256>>>(att_w1);
    softmax_att_kernel<<<B_, 32>>>(out);

    // --- graph readout + classifier ---
    graph_rep_kernel<<<(B_ * (2 * DOUT_ + D_) + T - 1) / T, T>>>(concat_cls);
    init_bias_kernel<<<(B_ * LH_ + T - 1) / T, T>>>(p_hid, lin1_b, B_, LH_);
    sgemm_acc<<<gemm_grid_f32(B_, LH_), 256>>>(p_rep, lin1_w, p_hid, B_, LH_, 2 * DOUT_ + D_);
    relu_kernel<<<(B_ * LH_ + T - 1) / T, T>>>(p_hid, (long long)B_ * LH_);
    final_kernel<<<B_, 128>>>(lin2_w, lin2_b, out);
}

// round 4
// speedup vs baseline: 2.1221x; 1.1503x over previous
#include <cuda_runtime.h>
#include <cuda_bf16.h>
#include <math.h>
#include <stdint.h>

// ---------------- problem constants ----------------
#define B_      64
#define EVI_    5
#define SEQS_   (B_ * EVI_)          // 320
#define L_      256
#define D_      768
#define WORDS_  32
#define TPW_    4
#define NN_     (SEQS_ * WORDS_)     // 10240 nodes
#define EE_     (NN_ * 16)           // 163840 edges
#define R_      4
#define DOUT_   768
#define LH_     1024
#define NC_     3
#define KTOT_   (5 * D_)             // 3840 fused K
#define NR_     (NN_ * R_)           // 40960 segments

// ---------------- scratch (device globals; no allocs allowed) ----------------
__device__ float g_x   [(size_t)NN_ * D_];          // x0 / x2
__device__ float g_acc [(size_t)NN_ * D_];          // x1
__device__ float g_h   [(size_t)R_ * NN_ * D_];     // per-relation aggregation
__device__ int   g_cnt [NR_];
__device__ int   g_off [NR_ + 1];
__device__ int   g_cur [NR_];
__device__ int   g_elist[EE_];
__device__ float g_ev  [SEQS_ * 2 * DOUT_];
__device__ float g_attin[SEQS_ * (D_ + 2 * DOUT_)];
__device__ float g_hatt[SEQS_ * DOUT_];
__device__ float g_p   [SEQS_];
__device__ float g_a   [SEQS_];
__device__ float g_rep [B_ * (2 * DOUT_ + D_)];
__device__ float g_hid [B_ * LH_];

// ---------------- utility kernels ----------------
__global__ void zero4_kernel(float4* p, long long n4) {
    long long t = (long long)blockIdx.x * blockDim.x + threadIdx.x;
    if (t < n4) p[t] = make_float4(0.f, 0.f, 0.f, 0.f);
}
__global__ void relu_kernel(float* p, long long n) {
    long long t = (long long)blockIdx.x * blockDim.x + threadIdx.x;
    if (t < n) p[t] = fmaxf(p[t], 0.f);
}
__global__ void init_bias_kernel(float* C, const float* __restrict__ bias, long long M, int N) {
    long long t = (long long)blockIdx.x * blockDim.x + threadIdx.x;
    if (t < M * N) C[t] = bias[t % N];
}

// ---------------- graph prep: counts -> scan -> scatter (CSR) ----------------
__global__ void count_kernel(const int* __restrict__ eidx, const int* __restrict__ etype) {
    int e = blockIdx.x * blockDim.x + threadIdx.x;
    if (e >= EE_) return;
    atomicAdd(&g_cnt[eidx[EE_ + e] * R_ + etype[e]], 1);
}
// single block, 1024 threads, 40 bins each (40960 total)
__global__ void scan_kernel() {
    __shared__ int part[1024];
    int tid = threadIdx.x;
    int base = tid * 40;
    int s = 0;
#pragma unroll 8
    for (int i = 0; i < 40; ++i) s += g_cnt[base + i];
    part[tid] = s;
    __syncthreads();
    for (int o = 1; o < 1024; o <<= 1) {
        int v = (tid >= o) ? part[tid - o] : 0;
        __syncthreads();
        part[tid] += v;
        __syncthreads();
    }
    int run = tid ? part[tid - 1] : 0;
#pragma unroll 8
    for (int i = 0; i < 40; ++i) {
        int c = g_cnt[base + i];
        g_off[base + i] = run;
        g_cur[base + i] = run;
        run += c;
    }
    if (tid == 1023) g_off[NR_] = run;
}
__global__ void scatter_kernel(const int* __restrict__ eidx, const int* __restrict__ etype) {
    int e = blockIdx.x * blockDim.x + threadIdx.x;
    if (e >= EE_) return;
    int src = eidx[e];
    int dst = eidx[EE_ + e];
    int r   = etype[e];
    int pos = atomicAdd(&g_cur[dst * R_ + r], 1);
    g_elist[pos] = src;
}

__global__ void gather_mean_kernel(const float* __restrict__ tok, const int* __restrict__ wti) {
    long long t = (long long)blockIdx.x * blockDim.x + threadIdx.x;
    if (t >= (long long)NN_ * D_) return;
    int n = (int)(t / D_);
    int d = (int)(t % D_);
    const int* w = wti + n * TPW_;
    float s = tok[(size_t)w[0] * D_ + d] + tok[(size_t)w[1] * D_ + d]
            + tok[(size_t)w[2] * D_ + d] + tok[(size_t)w[3] * D_ + d];
    g_x[t] = 0.25f * s;
}

// one CTA per dst node, 192 threads; thread owns 4 feature columns.
// writes h[r][dst][:] = mean over src of x[src][:] (or 0 if no edges) — no atomics, no pre-zero.
__global__ void __launch_bounds__(192)
csr_agg_kernel(const float* __restrict__ x) {
    int dst = blockIdx.x;
    int d = threadIdx.x * 4;
#pragma unroll
    for (int r = 0; r < R_; ++r) {
        int beg = g_off[dst * R_ + r];
        int end = g_off[dst * R_ + r + 1];
        float4 a = make_float4(0.f, 0.f, 0.f, 0.f);
        for (int i = beg; i < end; ++i) {
            int src = g_elist[i];
            float4 v = *(const float4*)(x + (size_t)src * D_ + d);
            a.x += v.x; a.y += v.y; a.z += v.z; a.w += v.w;
        }
        float s = (end > beg) ? (1.f / (float)(end - beg)) : 0.f;
        a.x *= s; a.y *= s; a.z *= s; a.w *= s;
        *(float4*)(g_h + ((size_t)r * NN_ + dst) * D_ + d) = a;
    }
}

// ---------------- split-bf16 tensor-core GEMM, software pipelined ----------------
// C(NN_ x 768) = relu( [h0|h1|h2|h3|x](NN_ x 3840) @ Wcat(3840 x 768) + bias )
#define GBM 128
#define GBN 128
#define GBK 32
#define NSTG (KTOT_ / GBK)   // 120
#define AP_  20              // A smem pitch (u32): 16 data + 4 pad (conflict-free)
#define BP_  136             // B smem pitch (u32): 128 data + 8 pad (136%32==8, conflict-free)
#define ASZ_ (GBM * AP_)     // 2560
#define BSZ_ (16 * BP_)      // 2176
#define SBUF (2 * ASZ_ + 2 * BSZ_)          // 9472 u32 per stage
#define GSMEM (2 * SBUF * 4)                // 75776 bytes

__device__ __forceinline__ uint32_t pack2(float lo, float hi) {
    uint32_t r;
    asm("cvt.rn.bf16x2.f32 %0, %1, %2;" : "=r"(r) : "f"(hi), "f"(lo));
    return r;
}
__device__ __forceinline__ void mma16816(float* c, const uint32_t* a, const uint32_t* b) {
    asm volatile("mma.sync.aligned.m16n8k16.row.col.f32.bf16.bf16.f32 "
                 "{%0,%1,%2,%3}, {%4,%5,%6,%7}, {%8,%9}, {%0,%1,%2,%3};"
                 : "+f"(c[0]), "+f"(c[1]), "+f"(c[2]), "+f"(c[3])
                 : "r"(a[0]), "r"(a[1]), "r"(a[2]), "r"(a[3]), "r"(b[0]), "r"(b[1]));
}

__global__ void __launch_bounds__(256, 1)
gemm_rgcn(const float* __restrict__ gh, const float* __restrict__ xroot,
          const float* __restrict__ Wrel, const float* __restrict__ Wroot,
          const float* __restrict__ bias, float* __restrict__ C) {
    extern __shared__ uint32_t sm[];
    const int tid  = threadIdx.x;
    const int wid  = tid >> 5;
    const int lane = tid & 31;
    const int g    = lane >> 2;
    const int tc   = lane & 3;
    const int wm   = wid & 3;        // 0..3 -> 32-row slice
    const int wn   = wid >> 2;       // 0..1 -> 64-col slice
    const int m0   = blockIdx.y * GBM;
    const int n0   = blockIdx.x * GBN;

    float acc[2][8][4];
#pragma unroll
    for (int i = 0; i < 2; ++i)
#pragma unroll
        for (int j = 0; j < 8; ++j)
#pragma unroll
            for (int q = 0; q < 4; ++q) acc[i][j][q] = 0.f;

    float4 pa[4], pb[4];

    // ---- prefetch helper (macro-free inline lambdas via local fns) ----
    auto prefetch = [&](int kc) {
        const int k0 = kc * GBK;
        const int r  = k0 / D_;
        const int d0 = k0 - r * D_;
        const float* Ab = (r < 4) ? (gh + ((size_t)r * NN_ + m0) * D_ + d0)
                                  : (xroot + (size_t)m0 * D_ + d0);
#pragma unroll
        for (int i = 0; i < 4; ++i) {
            int c = tid + i * 256;
            int m = c >> 3, kq = c & 7;
            pa[i] = *(const float4*)(Ab + (size_t)m * D_ + kq * 4);
        }
        const float* Wb = (r < 4) ? (Wrel + ((size_t)r * D_ + d0) * D_ + n0)
                                  : (Wroot + (size_t)d0 * D_ + n0);
#pragma unroll
        for (int i = 0; i < 2; ++i) {
            int c = tid + i * 256;        // c < 512
            int k2 = c >> 5, nq = (c & 31) * 4;
            const float* w0 = Wb + (size_t)(2 * k2) * D_ + nq;
            pb[2 * i]     = *(const float4*)w0;
            pb[2 * i + 1] = *(const float4*)(w0 + D_);
        }
    };
    auto store_stage = [&](uint32_t* buf) {
        uint32_t* AsH = buf;
        uint32_t* AsL = buf + ASZ_;
        uint32_t* BsH = buf + 2 * ASZ_;
        uint32_t* BsL = buf + 2 * ASZ_ + BSZ_;
#pragma unroll
        for (int i = 0; i < 4; ++i) {
            int c = tid + i * 256;
            int m = c >> 3, kq = c & 7;
            float4 v = pa[i];
            uint32_t h0 = pack2(v.x, v.y);
            uint32_t h1 = pack2(v.z, v.w);
            uint32_t l0 = pack2(v.x - __uint_as_float(h0 << 16),
                                v.y - __uint_as_float(h0 & 0xFFFF0000u));
            uint32_t l1 = pack2(v.z - __uint_as_float(h1 << 16),
                                v.w - __uint_as_float(h1 & 0xFFFF0000u));
            int off = m * AP_ + kq * 2;
            *(uint2*)&AsH[off] = make_uint2(h0, h1);
            *(uint2*)&AsL[off] = make_uint2(l0, l1);
        }
#pragma unroll
        for (int i = 0; i < 2; ++i) {
            int c = tid + i * 256;
            int k2 = c >> 5, nq = (c & 31) * 4;
            float4 va = pb[2 * i], vb = pb[2 * i + 1];
            uint32_t h0 = pack2(va.x, vb.x);
            uint32_t h1 = pack2(va.y, vb.y);
            uint32_t h2 = pack2(va.z, vb.z);
            uint32_t h3 = pack2(va.w, vb.w);
            uint32_t l0 = pack2(va.x - __uint_as_float(h0 << 16), vb.x - __uint_as_float(h0 & 0xFFFF0000u));
            uint32_t l1 = pack2(va.y - __uint_as_float(h1 << 16), vb.y - __uint_as_float(h1 & 0xFFFF0000u));
            uint32_t l2 = pack2(va.z - __uint_as_float(h2 << 16), vb.z - __uint_as_float(h2 & 0xFFFF0000u));
            uint32_t l3 = pack2(va.w - __uint_as_float(h3 << 16), vb.w - __uint_as_float(h3 & 0xFFFF0000u));
            int off = k2 * BP_ + nq;
            *(uint4*)&BsH[off] = make_uint4(h0, h1, h2, h3);
            *(uint4*)&BsL[off] = make_uint4(l0, l1, l2, l3);
        }
    };
    auto compute = [&](const uint32_t* buf) {
        const uint32_t* AsH = buf;
        const uint32_t* AsL = buf + ASZ_;
        const uint32_t* BsH = buf + 2 * ASZ_;
        const uint32_t* BsL = buf + 2 * ASZ_ + BSZ_;
#pragma unroll
        for (int ks = 0; ks < 2; ++ks) {
            const int kb = ks * 8;
            uint32_t aH[2][4], aL[2][4], bH[8][2], bL[8][2];
#pragma unroll
            for (int mt = 0; mt < 2; ++mt) {
                int rb = wm * 32 + mt * 16;
                int i0 = (rb + g) * AP_ + kb + tc;
                int i1 = i0 + 8 * AP_;
                aH[mt][0] = AsH[i0]; aH[mt][1] = AsH[i1];
                aH[mt][2] = AsH[i0 + 4]; aH[mt][3] = AsH[i1 + 4];
                aL[mt][0] = AsL[i0]; aL[mt][1] = AsL[i1];
                aL[mt][2] = AsL[i0 + 4]; aL[mt][3] = AsL[i1 + 4];
            }
#pragma unroll
            for (int nt = 0; nt < 8; ++nt) {
                int cb = wn * 64 + nt * 8;
                int j0 = (kb + tc) * BP_ + cb + g;
                int j1 = j0 + 4 * BP_;
                bH[nt][0] = BsH[j0]; bH[nt][1] = BsH[j1];
                bL[nt][0] = BsL[j0]; bL[nt][1] = BsL[j1];
            }
#pragma unroll
            for (int mt = 0; mt < 2; ++mt)
#pragma unroll
                for (int nt = 0; nt < 8; ++nt) {
                    mma16816(acc[mt][nt], aH[mt], bH[nt]);
                    mma16816(acc[mt][nt], aH[mt], bL[nt]);
                    mma16816(acc[mt][nt], aL[mt], bH[nt]);
                }
        }
    };

    // ---- pipeline ----
    prefetch(0);
    store_stage(sm);
    __syncthreads();
    for (int kc = 0; kc < NSTG; ++kc) {
        const int cur = kc & 1;
        if (kc + 1 < NSTG) prefetch(kc + 1);
        compute(sm + cur * SBUF);
        if (kc + 1 < NSTG) {
            store_stage(sm + (1 - cur) * SBUF);
            __syncthreads();
        }
    }

    // ---- epilogue: bias + relu ----
#pragma unroll
    for (int mt = 0; mt < 2; ++mt) {
        int row = m0 + wm * 32 + mt * 16 + g;
#pragma unroll
        for (int nt = 0; nt < 8; ++nt) {
            int col = n0 + wn * 64 + nt * 8 + tc * 2;
            float b0 = __ldg(bias + col);
            float b1 = __ldg(bias + col + 1);
            float2 v0 = make_float2(fmaxf(acc[mt][nt][0] + b0, 0.f),
                                    fmaxf(acc[mt][nt][1] + b1, 0.f));
            float2 v1 = make_float2(fmaxf(acc[mt][nt][2] + b0, 0.f),
                                    fmaxf(acc[mt][nt][3] + b1, 0.f));
            *(float2*)(C + (size_t)row * D_ + col)       = v0;
            *(float2*)(C + (size_t)(row + 8) * D_ + col) = v1;
        }
    }
}

// ---------------- fp32 SGEMM for small head GEMMs ----------------
#define BM 128
#define BN 128
#define BK 8
#define TM 8
#define TN 8
__global__ __launch_bounds__(256)
void sgemm_acc(const float* __restrict__ A, const float* __restrict__ Bm,
               float* __restrict__ C, int M, int N, int K) {
    const int brow = blockIdx.y, bcol = blockIdx.x;
    const int tid = threadIdx.x;
    __shared__ float As[BK][BM];
    __shared__ float Bs[BK][BN];
    const int threadRow = tid / (BN / TN);
    const int threadCol = tid % (BN / TN);
    const int aRow = tid >> 1;
    const int aCol = (tid & 1) * 4;
    const int bRow = tid >> 5;
    const int bCol = (tid & 31) * 4;
    float acc[TM][TN] = {};
    float regM[TM], regN[TN];
    const int gARow = brow * BM + aRow;
    const bool aValid = (gARow < M);
    const float* Aptr = A + (size_t)gARow * K;
    const float* Bptr = Bm + bcol * BN;
    for (int k0 = 0; k0 < K; k0 += BK) {
        float4 av = aValid ? *(const float4*)(Aptr + k0 + aCol) : make_float4(0.f, 0.f, 0.f, 0.f);
        As[aCol + 0][aRow] = av.x;
        As[aCol + 1][aRow] = av.y;
        As[aCol + 2][aRow] = av.z;
        As[aCol + 3][aRow] = av.w;
        *(float4*)&Bs[bRow][bCol] = *(const float4*)(Bptr + (size_t)(k0 + bRow) * N + bCol);
        __syncthreads();
#pragma unroll
        for (int k = 0; k < BK; ++k) {
#pragma unroll
            for (int i = 0; i < TM; ++i) regM[i] = As[k][threadRow * TM + i];
#pragma unroll
            for (int j = 0; j < TN; ++j) regN[j] = Bs[k][threadCol * TN + j];
#pragma unroll
            for (int i = 0; i < TM; ++i)
#pragma unroll
                for (int j = 0; j < TN; ++j)
                    acc[i][j] += regM[i] * regN[j];
        }
        __syncthreads();
    }
#pragma unroll
    for (int i = 0; i < TM; ++i) {
        int r = brow * BM + threadRow * TM + i;
        if (r < M) {
            float* Cp = C + (size_t)r * N + bcol * BN + threadCol * TN;
#pragma unroll
            for (int j = 0; j < TN; j += 4) {
                float4 cv = *(float4*)(Cp + j);
                cv.x += acc[i][j + 0];
                cv.y += acc[i][j + 1];
                cv.z += acc[i][j + 2];
                cv.w += acc[i][j + 3];
                *(float4*)(Cp + j) = cv;
            }
        }
    }
}

// ---------------- head kernels ----------------
__global__ void ev_pool_kernel() {
    int t = blockIdx.x * blockDim.x + threadIdx.x;
    if (t >= SEQS_ * DOUT_) return;
    int s = t / DOUT_, d = t % DOUT_;
    const float* base = g_x + (size_t)s * WORDS_ * DOUT_ + d;
    float sum = 0.f, mx = -1e30f;
#pragma unroll 8
    for (int w = 0; w < WORDS_; ++w) {
        float v = base[(size_t)w * DOUT_];
        sum += v;
        mx = fmaxf(mx, v);
    }
    g_ev[s * (2 * DOUT_) + d]         = sum * (1.f / WORDS_);
    g_ev[s * (2 * DOUT_) + DOUT_ + d] = mx;
}
__global__ void build_attin_kernel(const float* __restrict__ tok, const int* __restrict__ csi) {
    int t = blockIdx.x * blockDim.x + threadIdx.x;
    const int W = D_ + 2 * DOUT_;
    if (t >= SEQS_ * W) return;
    int s = t / W, c = t % W;
    if (c < D_) {
        int seq = csi[s / EVI_];
        g_attin[t] = tok[(size_t)seq * L_ * D_ + c];
    } else {
        g_attin[t] = g_ev[s * (2 * DOUT_) + (c - D_)];
    }
}
__global__ void dotp_kernel(const float* __restrict__ att_w1) {
    int s = blockIdx.x;
    int tid = threadIdx.x;
    float acc = 0.f;
    for (int k = tid; k < DOUT_; k += 256)
        acc += g_hatt[(size_t)s * DOUT_ + k] * att_w1[k];
#pragma unroll
    for (int o = 16; o; o >>= 1) acc += __shfl_down_sync(0xffffffffu, acc, o);
    __shared__ float sw[8];
    if ((tid & 31) == 0) sw[tid >> 5] = acc;
    __syncthreads();
    if (tid == 0) {
        float r = 0.f;
#pragma unroll
        for (int w = 0; w < 8; ++w) r += sw[w];
        g_p[s] = r;
    }
}
__global__ void softmax_att_kernel(float* __restrict__ out) {
    int b = blockIdx.x;
    if (threadIdx.x != 0) return;
    float pv[EVI_];
    float m = -1e30f;
#pragma unroll
    for (int e = 0; e < EVI_; ++e) { pv[e] = g_p[b * EVI_ + e]; m = fmaxf(m, pv[e]); }
    float s = 0.f;
#pragma unroll
    for (int e = 0; e < EVI_; ++e) { pv[e] = expf(pv[e] - m); s += pv[e]; }
    float is = 1.f / s;
#pragma unroll
    for (int e = 0; e < EVI_; ++e) {
        g_a[b * EVI_ + e] = pv[e] * is;
        float p = g_p[b * EVI_ + e];
        out[B_ * NC_ + b * EVI_ + e] = 1.f / (1.f + expf(-p));
    }
}
__global__ void graph_rep_kernel(const float* __restrict__ concat_cls) {
    int t = blockIdx.x * blockDim.x + threadIdx.x;
    const int W = 2 * DOUT_ + D_;
    if (t >= B_ * W) return;
    int b = t / W, c = t % W;
    if (c < 2 * DOUT_) {
        float acc = 0.f;
#pragma unroll
        for (int e = 0; e < EVI_; ++e)
            acc += g_a[b * EVI_ + e] * g_ev[(size_t)(b * EVI_ + e) * (2 * DOUT_) + c];
        g_rep[t] = acc;
    } else {
        g_rep[t] = concat_cls[b * D_ + (c - 2 * DOUT_)];
    }
}
__global__ void final_kernel(const float* __restrict__ lin2_w,
                             const float* __restrict__ lin2_b,
                             float* __restrict__ out) {
    int b = blockIdx.x;
    int tid = threadIdx.x;
    float a0 = 0.f, a1 = 0.f, a2 = 0.f;
    for (int k = tid; k < LH_; k += 128) {
        float h = g_hid[(size_t)b * LH_ + k];
        a0 += h * lin2_w[k * NC_ + 0];
        a1 += h * lin2_w[k * NC_ + 1];
        a2 += h * lin2_w[k * NC_ + 2];
    }
#pragma unroll
    for (int o = 16; o; o >>= 1) {
        a0 += __shfl_down_sync(0xffffffffu, a0, o);
        a1 += __shfl_down_sync(0xffffffffu, a1, o);
        a2 += __shfl_down_sync(0xffffffffu, a2, o);
    }
    __shared__ float s0[4], s1[4], s2[4];
    if ((tid & 31) == 0) { int w = tid >> 5; s0[w] = a0; s1[w] = a1; s2[w] = a2; }
    __syncthreads();
    if (tid == 0) {
        float l0 = s0[0] + s0[1] + s0[2] + s0[3] + lin2_b[0];
        float l1 = s1[0] + s1[1] + s1[2] + s1[3] + lin2_b[1];
        float l2 = s2[0] + s2[1] + s2[2] + s2[3] + lin2_b[2];
        float m = fmaxf(l0, fmaxf(l1, l2));
        float lse = logf(expf(l0 - m) + expf(l1 - m) + expf(l2 - m)) + m;
        out[b * NC_ + 0] = l0 - lse;
        out[b * NC_ + 1] = l1 - lse;
        out[b * NC_ + 2] = l2 - lse;
    }
}

// ---------------- launch ----------------
static inline dim3 gemm_grid_f32(int M, int N) {
    return dim3((N + BN - 1) / BN, (M + BM - 1) / BM);
}

extern "C" void kernel_launch(void* const* d_in, const int* in_sizes, int n_in,
                              void* d_out, int out_size) {
    const float* token_feats = (const float*)d_in[0];
    const float* concat_cls  = (const float*)d_in[1];
    const float* W_rel1      = (const float*)d_in[2];
    const float* W_root1     = (const float*)d_in[3];
    const float* b1          = (const float*)d_in[4];
    const float* W_rel2      = (const float*)d_in[5];
    const float* W_root2     = (const float*)d_in[6];
    const float* b2          = (const float*)d_in[7];
    const float* att_w0      = (const float*)d_in[8];
    const float* att_w1      = (const float*)d_in[9];
    const float* lin1_w      = (const float*)d_in[10];
    const float* lin1_b      = (const float*)d_in[11];
    const float* lin2_w      = (const float*)d_in[12];
    const float* lin2_b      = (const float*)d_in[13];
    const int*   wti         = (const int*)d_in[14];
    const int*   eidx        = (const int*)d_in[15];
    const int*   etype       = (const int*)d_in[16];
    const int*   csi         = (const int*)d_in[17];
    float* out = (float*)d_out;

    float *p_x, *p_acc, *p_h, *p_attin, *p_hatt, *p_rep, *p_hid;
    int* p_cnt;
    cudaGetSymbolAddress((void**)&p_x,     g_x);
    cudaGetSymbolAddress((void**)&p_acc,   g_acc);
    cudaGetSymbolAddress((void**)&p_h,     g_h);
    cudaGetSymbolAddress((void**)&p_cnt,   g_cnt);
    cudaGetSymbolAddress((void**)&p_attin, g_attin);
    cudaGetSymbolAddress((void**)&p_hatt,  g_hatt);
    cudaGetSymbolAddress((void**)&p_rep,   g_rep);
    cudaGetSymbolAddress((void**)&p_hid,   g_hid);

    cudaFuncSetAttribute(gemm_rgcn, cudaFuncAttributeMaxDynamicSharedMemorySize, GSMEM);

    const int T = 256;
    const long long ND = (long long)NN_ * D_;
    const dim3 ggrid(D_ / GBN, NN_ / GBM);   // (6, 80)

    // --- graph prep: CSR build (per-launch deterministic up to fp-sum order) ---
    zero4_kernel<<<(NR_ / 4 + T - 1) / T, T>>>((float4*)p_cnt, NR_ / 4);
    count_kernel<<<(EE_ + T - 1) / T, T>>>(eidx, etype);
    scan_kernel<<<1, 1024>>>();
    scatter_kernel<<<(EE_ + T - 1) / T, T>>>(eidx, etype);

    // --- x0 ---
    gather_mean_kernel<<<(unsigned)((ND + T - 1) / T), T>>>(token_feats, wti);

    // --- layer 1 ---
    csr_agg_kernel<<<NN_, 192>>>(p_x);
    gemm_rgcn<<<ggrid, 256, GSMEM>>>(p_h, p_x, W_rel1, W_root1, b1, p_acc);

    // --- layer 2 ---
    csr_agg_kernel<<<NN_, 192>>>(p_acc);
    gemm_rgcn<<<ggrid, 256, GSMEM>>>(p_h, p_acc, W_rel2, W_root2, b2, p_x);

    // --- evidence pooling + attention ---
    ev_pool_kernel<<<(SEQS_ * DOUT_ + T - 1) / T, T>>>();
    build_attin_kernel<<<(SEQS_ * (D_ + 2 * DOUT_) + T - 1) / T, T>>>(token_feats, csi);
    zero4_kernel<<<(SEQS_ * DOUT_ / 4 + T - 1) / T, T>>>((float4*)p_hatt, SEQS_ * DOUT_ / 4);
    sgemm_acc<<<gemm_grid_f32(SEQS_, DOUT_), 256>>>(p_attin, att_w0, p_hatt,
                                                    SEQS_, DOUT_, D_ + 2 * DOUT_);
    relu_kernel<<<(SEQS_ * DOUT_ + T - 1) / T, T>>>(p_hatt, (long long)SEQS_ * DOUT_);
    dotp_kernel<<<SEQS_, 256>>>(att_w1);
    softmax_att_kernel<<<B_, 32>>>(out);

    // --- graph readout + classifier ---
    graph_rep_kernel<<<(B_ * (2 * DOUT_ + D_) + T - 1) / T, T>>>(concat_cls);
    init_bias_kernel<<<(B_ * LH_ + T - 1) / T, T>>>(p_hid, lin1_b, B_, LH_);
    sgemm_acc<<<gemm_grid_f32(B_, LH_), 256>>>(p_rep, lin1_w, p_hid, B_, LH_, 2 * DOUT_ + D_);
    relu_kernel<<<(B_ * LH_ + T - 1) / T, T>>>(p_hid, (long long)B_ * LH_);
    final_kernel<<<B_, 128>>>(lin2_w, lin2_b, out);
}